// round 3
// baseline (speedup 1.0000x reference)
#include <cuda_runtime.h>
#include <cuda_bf16.h>
#include <cstdint>
#include <cstddef>

#define NTOK 4096
#define HDIM 1024
#define IDIM 4096
#define NEXP 8

typedef __nv_bfloat16 bf16;

// ------------------------- scratch (static device, no allocs) -------------------------
__device__ bf16 g_x_hi[(size_t)NTOK * HDIM];
__device__ bf16 g_x_lo[(size_t)NTOK * HDIM];
__device__ bf16 g_w1_hi[(size_t)NEXP * IDIM * HDIM];
__device__ bf16 g_w1_lo[(size_t)NEXP * IDIM * HDIM];
__device__ bf16 g_w2_hi[(size_t)NEXP * HDIM * IDIM];
__device__ bf16 g_w2_lo[(size_t)NEXP * HDIM * IDIM];
__device__ bf16 g_mid_hi[(size_t)NTOK * IDIM];
__device__ bf16 g_mid_lo[(size_t)NTOK * IDIM];
__device__ float g_probs[NTOK * NEXP];

// ------------------------- arch-neutral PTX helpers -------------------------
__device__ __forceinline__ uint32_t smem_u32(const void* p) {
    uint32_t a;
    asm("{ .reg .u64 t; cvta.to.shared.u64 t, %1; cvt.u32.u64 %0, t; }" : "=r"(a) : "l"(p));
    return a;
}

__device__ __forceinline__ void cp_async16(uint32_t smem, const void* g) {
    asm volatile("cp.async.cg.shared.global [%0], [%1], 16;\n" :: "r"(smem), "l"(g));
}

// swizzle for 128B rows: off ^ ((row&7)<<4), with off = row*128 + colbyte
__device__ __forceinline__ uint32_t swz_row(uint32_t row, uint32_t colbyte) {
    return row * 128u + (colbyte ^ ((row & 7u) << 4));
}

__device__ __forceinline__ void ldsm_x4(uint32_t (&r)[4], uint32_t addr) {
    asm volatile("ldmatrix.sync.aligned.m8n8.x4.shared.b16 {%0,%1,%2,%3}, [%4];"
                 : "=r"(r[0]), "=r"(r[1]), "=r"(r[2]), "=r"(r[3]) : "r"(addr));
}

__device__ __forceinline__ void mma16816(float (&d)[4], const uint32_t (&a)[4],
                                         const uint32_t (&b)[2]) {
    asm volatile(
        "mma.sync.aligned.m16n8k16.row.col.f32.bf16.bf16.f32 "
        "{%0,%1,%2,%3}, {%4,%5,%6,%7}, {%8,%9}, {%0,%1,%2,%3};"
        : "+f"(d[0]), "+f"(d[1]), "+f"(d[2]), "+f"(d[3])
        : "r"(a[0]), "r"(a[1]), "r"(a[2]), "r"(a[3]), "r"(b[0]), "r"(b[1]));
}

// ------------------------- tcgen05 helpers (103a-gated) -------------------------
#if defined(__CUDA_ARCH__) && defined(__CUDA_ARCH_FEAT_SM103_ALL)
#define HAVE_TCGEN05 1

__device__ __forceinline__ uint32_t elect_one() {
    uint32_t pred;
    asm volatile("{\n\t.reg .pred p;\n\telect.sync _|p, 0xFFFFFFFF;\n\tselp.b32 %0, 1, 0, p;\n\t}"
                 : "=r"(pred));
    return pred;
}

__device__ __forceinline__ void mbar_init(uint32_t addr, uint32_t cnt) {
    asm volatile("mbarrier.init.shared.b64 [%0], %1;" :: "r"(addr), "r"(cnt) : "memory");
}

__device__ __forceinline__ void mbar_wait(uint32_t addr, uint32_t phase) {
    asm volatile(
        "{\n\t.reg .pred P;\n\t"
        "WL_%=:\n\t"
        "mbarrier.try_wait.parity.acquire.cta.shared::cta.b64 P, [%0], %1, 0x989680;\n\t"
        "@P bra.uni WD_%=;\n\t"
        "bra.uni WL_%=;\n\t"
        "WD_%=:\n\t}"
        :: "r"(addr), "r"(phase) : "memory");
}

__device__ __forceinline__ void mma_f16_ss_cg1(uint32_t d, uint64_t ad, uint64_t bd,
                                               uint32_t idesc, uint32_t acc) {
    asm volatile(
        "{\n\t.reg .pred p;\n\tsetp.ne.u32 p, %5, 0;\n\t"
        "tcgen05.mma.cta_group::1.kind::f16 [%0], %1, %2, %3, {%4, %4, %4, %4}, p;\n\t}"
        :: "r"(d), "l"(ad), "l"(bd), "r"(idesc), "r"(0u), "r"(acc)
        : "memory");
}

__device__ __forceinline__ void tc_commit(uint32_t mbar) {
    asm volatile(
        "tcgen05.commit.cta_group::1.mbarrier::arrive::one.shared::cluster.b64 [%0];"
        :: "r"(mbar) : "memory");
}

#define TC_ALLOC(sa, n)  asm volatile("tcgen05.alloc.cta_group::1.sync.aligned.shared::cta.b32 [%0], %1;" :: "r"(sa), "r"((uint32_t)(n)) : "memory")
#define TC_DEALLOC(t, n) asm volatile("tcgen05.dealloc.cta_group::1.sync.aligned.b32 %0, %1;" :: "r"(t), "r"((uint32_t)(n)))
#define TC_RELINQ()      asm volatile("tcgen05.relinquish_alloc_permit.cta_group::1.sync.aligned;")
#define TC_WAIT_LD()     asm volatile("tcgen05.wait::ld.sync.aligned;" ::: "memory")
#define TC_FENCE_AFTER() asm volatile("tcgen05.fence::after_thread_sync;" ::: "memory")

#define TC_LD_X32(r, addr) \
    asm volatile("tcgen05.ld.sync.aligned.32x32b.x32.b32 " \
        "{%0, %1, %2, %3, %4, %5, %6, %7, %8, %9, %10, %11, %12, %13, %14, %15, " \
        " %16, %17, %18, %19, %20, %21, %22, %23, %24, %25, %26, %27, %28, %29, %30, %31}, [%32];" \
        : "=r"((r)[0]), "=r"((r)[1]), "=r"((r)[2]), "=r"((r)[3]), "=r"((r)[4]), "=r"((r)[5]), \
          "=r"((r)[6]), "=r"((r)[7]), "=r"((r)[8]), "=r"((r)[9]), "=r"((r)[10]), "=r"((r)[11]), \
          "=r"((r)[12]), "=r"((r)[13]), "=r"((r)[14]), "=r"((r)[15]), "=r"((r)[16]), "=r"((r)[17]), \
          "=r"((r)[18]), "=r"((r)[19]), "=r"((r)[20]), "=r"((r)[21]), "=r"((r)[22]), "=r"((r)[23]), \
          "=r"((r)[24]), "=r"((r)[25]), "=r"((r)[26]), "=r"((r)[27]), "=r"((r)[28]), "=r"((r)[29]), \
          "=r"((r)[30]), "=r"((r)[31]) \
        : "r"(addr))

__device__ __forceinline__ uint64_t make_desc_sw128(uint32_t base) {
    const uint64_t BASE =
        (uint64_t(2) << 61) | (uint64_t(1) << 46) | (uint64_t(64) << 32) | (uint64_t(1) << 16);
    return BASE | ((uint64_t)(base >> 4) & 0x3FFF);
}
#else
#define HAVE_TCGEN05 0
#endif

// ------------------------- split kernel: fp32 -> (bf16 hi, bf16 lo) -------------------------
__global__ void moe_split_kernel(const float* __restrict__ src, bf16* __restrict__ hi,
                                 bf16* __restrict__ lo, size_t n8) {
    size_t i = (size_t)blockIdx.x * blockDim.x + threadIdx.x;
    size_t stride = (size_t)gridDim.x * blockDim.x;
    for (; i < n8; i += stride) {
        const float4* s = (const float4*)(src + i * 8);
        float4 a = s[0], b = s[1];
        float v[8] = {a.x, a.y, a.z, a.w, b.x, b.y, b.z, b.w};
        union { bf16 h[8]; uint4 u; } H, L;
        #pragma unroll
        for (int j = 0; j < 8; ++j) {
            bf16 h = __float2bfloat16(v[j]);
            H.h[j] = h;
            L.h[j] = __float2bfloat16(v[j] - __bfloat162float(h));
        }
        *(uint4*)(hi + i * 8) = H.u;
        *(uint4*)(lo + i * 8) = L.u;
    }
}

// ------------------------- router: logits -> softmax -> sort desc -------------------------
__global__ void moe_router_kernel(const float* __restrict__ hs, const float* __restrict__ Wr,
                                  float* __restrict__ probs) {
    int warp = threadIdx.x >> 5, lane = threadIdx.x & 31;
    int n = blockIdx.x * 4 + warp;
    if (n >= NTOK) return;
    const float* x = hs + (size_t)n * HDIM;
    float acc[NEXP];
    #pragma unroll
    for (int e = 0; e < NEXP; ++e) acc[e] = 0.f;
    for (int j = lane; j < HDIM; j += 32) {
        float xv = x[j];
        #pragma unroll
        for (int e = 0; e < NEXP; ++e) acc[e] += xv * Wr[e * HDIM + j];
    }
    #pragma unroll
    for (int off = 16; off; off >>= 1) {
        #pragma unroll
        for (int e = 0; e < NEXP; ++e)
            acc[e] += __shfl_down_sync(0xffffffffu, acc[e], off);
    }
    if (lane == 0) {
        float m = acc[0];
        #pragma unroll
        for (int e = 1; e < NEXP; ++e) m = fmaxf(m, acc[e]);
        float s = 0.f, p[NEXP];
        #pragma unroll
        for (int e = 0; e < NEXP; ++e) { p[e] = expf(acc[e] - m); s += p[e]; }
        float inv = 1.f / s;
        #pragma unroll
        for (int e = 0; e < NEXP; ++e) p[e] *= inv;
        #pragma unroll
        for (int i = 1; i < NEXP; ++i) {
            float key = p[i];
            int j = i - 1;
            while (j >= 0 && p[j] < key) { p[j + 1] = p[j]; --j; }
            p[j + 1] = key;
        }
        #pragma unroll
        for (int e = 0; e < NEXP; ++e) probs[n * NEXP + e] = p[e];
    }
}

// ------------------------- fused bf16x3 GEMM (tcgen05 or mma.sync fallback) ----------------
// Tile 128x128, K-chunk 64, double-buffered cp.async.
// D[m,n] = sum over 3 phases (hi*hi, hi*lo, lo*hi) of A-phase[m,k]*B-phase[n,k].
// mode 0: mid = split(gelu(D))   mode 1: out (+)= prob[m,e] * D
__global__ void __launch_bounds__(128, 2) moe_gemm(
    const bf16* __restrict__ Ahi, const bf16* __restrict__ Alo,
    const bf16* __restrict__ Bhi, const bf16* __restrict__ Blo,
    int K, int mode, int eidx,
    bf16* __restrict__ midhi, bf16* __restrict__ midlo,
    float* __restrict__ outp, const float* __restrict__ probs) {
    constexpr int MT = 128;
    constexpr int NT = 128;
    constexpr int A_BYTES = MT * 128;
    constexpr int B_BYTES = NT * 128;
    constexpr int STAGE = A_BYTES + B_BYTES;

    extern __shared__ char dsm[];

    const int tid = threadIdx.x, wid = tid >> 5, lane = tid & 31;
    const int m0 = blockIdx.x * MT;
    const int n0 = blockIdx.y * NT;

    uint32_t tiles = (smem_u32(dsm) + 1023u) & ~1023u;

    const int kc = K / 64;   // 64-element K chunks per phase
    const int NC = 3 * kc;

    auto load_chunk = [&](int c, int b) {
        int p = c / kc;
        int kk = (c - p * kc) * 64;
        const bf16* As = (p < 2) ? Ahi : Alo;
        const bf16* Bs = (p == 1) ? Blo : Bhi;
        uint32_t sA = tiles + b * STAGE;
        uint32_t sB = sA + A_BYTES;
        #pragma unroll
        for (int v = 0; v < MT * 8 / 128; ++v) {
            int idx = v * 128 + tid;
            int r = idx >> 3, c16 = idx & 7;
            const void* g = As + (size_t)(m0 + r) * K + kk + c16 * 8;
            cp_async16(sA + swz_row((uint32_t)r, (uint32_t)(c16 * 16)), g);
        }
        #pragma unroll
        for (int v = 0; v < NT * 8 / 128; ++v) {
            int idx = v * 128 + tid;
            int r = idx >> 3, c16 = idx & 7;
            const void* g = Bs + (size_t)(n0 + r) * K + kk + c16 * 8;
            cp_async16(sB + swz_row((uint32_t)r, (uint32_t)(c16 * 16)), g);
        }
        asm volatile("cp.async.commit_group;\n" ::: "memory");
    };

#if HAVE_TCGEN05
    // ================= tcgen05 path =================
    __shared__ uint32_t s_tmem;
    __shared__ __align__(8) uint64_t s_mbar[2];
    constexpr uint32_t IDESC =
        (1u << 4) | (1u << 7) | (1u << 10) | ((uint32_t)(NT / 8) << 17) | ((uint32_t)(MT / 16) << 24);

    uint32_t mb0 = smem_u32(&s_mbar[0]);
    uint32_t mb1 = smem_u32(&s_mbar[1]);
    if (wid == 0) {
        TC_ALLOC(smem_u32(&s_tmem), NT);
        TC_RELINQ();
    }
    if (tid == 0) { mbar_init(mb0, 1); mbar_init(mb1, 1); }
    __syncthreads();
    const uint32_t tmem = s_tmem;

    load_chunk(0, 0);
    load_chunk(1, 1);
    uint32_t ph[2] = {0u, 0u};

    for (int c = 0; c < NC; ++c) {
        int b = c & 1;
        if (c + 1 < NC) asm volatile("cp.async.wait_group 1;\n" ::: "memory");
        else            asm volatile("cp.async.wait_group 0;\n" ::: "memory");
        asm volatile("fence.proxy.async.shared::cta;\n" ::: "memory");
        __syncthreads();
        if (wid == 0) {
            uint32_t sA = tiles + b * STAGE;
            uint64_t ad = make_desc_sw128(sA);
            uint64_t bd = make_desc_sw128(sA + A_BYTES);
            if (elect_one()) {
                #pragma unroll
                for (int k = 0; k < 4; ++k)
                    mma_f16_ss_cg1(tmem, ad + k * 2, bd + k * 2, IDESC,
                                   (uint32_t)((c > 0) || (k > 0)));
                tc_commit(b ? mb1 : mb0);
            }
        }
        mbar_wait(b ? mb1 : mb0, ph[b]);
        ph[b] ^= 1u;
        if (c + 2 < NC) load_chunk(c + 2, b);
    }

    TC_FENCE_AFTER();
    const int row = m0 + wid * 32 + lane;

    if (mode == 0) {
        for (int cb = 0; cb < NT; cb += 32) {
            uint32_t r[32];
            TC_LD_X32(r, tmem + cb);
            TC_WAIT_LD();
            union { __nv_bfloat162 h2[16]; uint4 u[4]; } H, L;
            #pragma unroll
            for (int j = 0; j < 16; ++j) {
                float v0 = __uint_as_float(r[2 * j]);
                float v1 = __uint_as_float(r[2 * j + 1]);
                float g0 = 0.5f * v0 * (1.0f + erff(v0 * 0.70710678118654752f));
                float g1 = 0.5f * v1 * (1.0f + erff(v1 * 0.70710678118654752f));
                bf16 h0 = __float2bfloat16(g0), h1 = __float2bfloat16(g1);
                bf16 l0 = __float2bfloat16(g0 - __bfloat162float(h0));
                bf16 l1 = __float2bfloat16(g1 - __bfloat162float(h1));
                H.h2[j] = __nv_bfloat162(h0, h1);
                L.h2[j] = __nv_bfloat162(l0, l1);
            }
            size_t base = (size_t)row * IDIM + n0 + cb;
            uint4* dh = (uint4*)(midhi + base);
            uint4* dl = (uint4*)(midlo + base);
            #pragma unroll
            for (int q = 0; q < 4; ++q) { dh[q] = H.u[q]; dl[q] = L.u[q]; }
        }
    } else {
        float pw = probs[row * NEXP + eidx];
        for (int cb = 0; cb < NT; cb += 32) {
            uint32_t r[32];
            TC_LD_X32(r, tmem + cb);
            TC_WAIT_LD();
            size_t base = (size_t)row * HDIM + n0 + cb;
            float4* o = (float4*)(outp + base);
            #pragma unroll
            for (int j = 0; j < 8; ++j) {
                float4 v;
                v.x = __uint_as_float(r[4 * j + 0]) * pw;
                v.y = __uint_as_float(r[4 * j + 1]) * pw;
                v.z = __uint_as_float(r[4 * j + 2]) * pw;
                v.w = __uint_as_float(r[4 * j + 3]) * pw;
                if (eidx > 0) {
                    float4 old = o[j];
                    v.x += old.x; v.y += old.y; v.z += old.z; v.w += old.w;
                }
                o[j] = v;
            }
        }
    }

    __syncthreads();
    if (wid == 0) TC_DEALLOC(tmem, NT);

#else
    // ================= mma.sync fallback path (sm_80+ legal) =================
    // 4 warps in 2x2 grid; warp tile 64x64; 32x HMMA m16n8k16 per k16-step.
    const int wm = (wid & 1) * 64;
    const int wn = (wid >> 1) * 64;

    float acc[4][8][4];
    #pragma unroll
    for (int mt = 0; mt < 4; ++mt)
        #pragma unroll
        for (int nt = 0; nt < 8; ++nt)
            #pragma unroll
            for (int q = 0; q < 4; ++q) acc[mt][nt][q] = 0.f;

    // per-lane ldmatrix address components
    const uint32_t rA = (((uint32_t)lane >> 3) & 1u) * 8u + ((uint32_t)lane & 7u);
    const uint32_t kA0 = (((uint32_t)lane >> 4) & 1u) * 16u;
    const uint32_t rB = (((uint32_t)lane >> 4) & 1u) * 8u + ((uint32_t)lane & 7u);
    const uint32_t kB0 = (((uint32_t)lane >> 3) & 1u) * 16u;

    load_chunk(0, 0);
    load_chunk(1, 1);

    for (int c = 0; c < NC; ++c) {
        int b = c & 1;
        if (c + 1 < NC) asm volatile("cp.async.wait_group 1;\n" ::: "memory");
        else            asm volatile("cp.async.wait_group 0;\n" ::: "memory");
        __syncthreads();

        uint32_t sA = tiles + b * STAGE;
        uint32_t sB = sA + A_BYTES;

        #pragma unroll
        for (int ks = 0; ks < 4; ++ks) {
            uint32_t af[4][4];
            #pragma unroll
            for (int mt = 0; mt < 4; ++mt) {
                uint32_t row = (uint32_t)(wm + mt * 16) + rA;
                ldsm_x4(af[mt], sA + swz_row(row, (uint32_t)(ks * 32) + kA0));
            }
            uint32_t bf[8][2];
            #pragma unroll
            for (int nt2 = 0; nt2 < 4; ++nt2) {
                uint32_t t[4];
                uint32_t row = (uint32_t)(wn + nt2 * 16) + rB;
                ldsm_x4(t, sB + swz_row(row, (uint32_t)(ks * 32) + kB0));
                bf[2 * nt2][0] = t[0]; bf[2 * nt2][1] = t[1];
                bf[2 * nt2 + 1][0] = t[2]; bf[2 * nt2 + 1][1] = t[3];
            }
            #pragma unroll
            for (int mt = 0; mt < 4; ++mt)
                #pragma unroll
                for (int nt = 0; nt < 8; ++nt)
                    mma16816(acc[mt][nt], af[mt], bf[nt]);
        }

        __syncthreads();
        if (c + 2 < NC) load_chunk(c + 2, b);
    }

    // epilogue
    const int rbase = m0 + wm + (lane >> 2);
    const int cbase = n0 + wn + (lane & 3) * 2;

    if (mode == 0) {
        #pragma unroll
        for (int mt = 0; mt < 4; ++mt) {
            #pragma unroll
            for (int half = 0; half < 2; ++half) {
                int row = rbase + mt * 16 + half * 8;
                size_t base = (size_t)row * IDIM;
                #pragma unroll
                for (int nt = 0; nt < 8; ++nt) {
                    int col = cbase + nt * 8;
                    float v0 = acc[mt][nt][half * 2 + 0];
                    float v1 = acc[mt][nt][half * 2 + 1];
                    float g0 = 0.5f * v0 * (1.0f + erff(v0 * 0.70710678118654752f));
                    float g1 = 0.5f * v1 * (1.0f + erff(v1 * 0.70710678118654752f));
                    bf16 h0 = __float2bfloat16(g0), h1 = __float2bfloat16(g1);
                    bf16 l0 = __float2bfloat16(g0 - __bfloat162float(h0));
                    bf16 l1 = __float2bfloat16(g1 - __bfloat162float(h1));
                    *(__nv_bfloat162*)(midhi + base + col) = __nv_bfloat162(h0, h1);
                    *(__nv_bfloat162*)(midlo + base + col) = __nv_bfloat162(l0, l1);
                }
            }
        }
    } else {
        #pragma unroll
        for (int mt = 0; mt < 4; ++mt) {
            #pragma unroll
            for (int half = 0; half < 2; ++half) {
                int row = rbase + mt * 16 + half * 8;
                float pw = probs[row * NEXP + eidx];
                size_t base = (size_t)row * HDIM;
                #pragma unroll
                for (int nt = 0; nt < 8; ++nt) {
                    int col = cbase + nt * 8;
                    float2 v;
                    v.x = acc[mt][nt][half * 2 + 0] * pw;
                    v.y = acc[mt][nt][half * 2 + 1] * pw;
                    if (eidx > 0) {
                        float2 old = *(float2*)(outp + base + col);
                        v.x += old.x; v.y += old.y;
                    }
                    *(float2*)(outp + base + col) = v;
                }
            }
        }
    }
#endif
}

// ------------------------- host launch -------------------------
extern "C" void kernel_launch(void* const* d_in, const int* in_sizes, int n_in,
                              void* d_out, int out_size) {
    const float* hs = (const float*)d_in[0];
    const float* Wr = (const float*)d_in[1];
    const float* W1 = (const float*)d_in[2];
    const float* W2 = (const float*)d_in[3];
    float* outp = (float*)d_out;

    void *xh, *xl, *w1h, *w1l, *w2h, *w2l, *mh, *ml, *pp;
    cudaGetSymbolAddress(&xh, g_x_hi);
    cudaGetSymbolAddress(&xl, g_x_lo);
    cudaGetSymbolAddress(&w1h, g_w1_hi);
    cudaGetSymbolAddress(&w1l, g_w1_lo);
    cudaGetSymbolAddress(&w2h, g_w2_hi);
    cudaGetSymbolAddress(&w2l, g_w2_lo);
    cudaGetSymbolAddress(&mh, g_mid_hi);
    cudaGetSymbolAddress(&ml, g_mid_lo);
    cudaGetSymbolAddress(&pp, g_probs);

    const int SMEM = 1024 + 2 * (128 * 128 + 128 * 128);  // 66560
    cudaFuncSetAttribute((const void*)moe_gemm,
                         cudaFuncAttributeMaxDynamicSharedMemorySize, SMEM);

    moe_split_kernel<<<2048, 256>>>(hs, (bf16*)xh, (bf16*)xl, (size_t)NTOK * HDIM / 8);
    moe_split_kernel<<<4096, 256>>>(W1, (bf16*)w1h, (bf16*)w1l, (size_t)NEXP * IDIM * HDIM / 8);
    moe_split_kernel<<<4096, 256>>>(W2, (bf16*)w2h, (bf16*)w2l, (size_t)NEXP * HDIM * IDIM / 8);
    moe_router_kernel<<<NTOK / 4, 128>>>(hs, Wr, (float*)pp);

    for (int e = 0; e < NEXP; ++e) {
        size_t off1 = (size_t)e * IDIM * HDIM;
        size_t off2 = (size_t)e * HDIM * IDIM;
        moe_gemm<<<dim3(NTOK / 128, IDIM / 128), 128, SMEM>>>(
            (const bf16*)xh, (const bf16*)xl,
            (const bf16*)w1h + off1, (const bf16*)w1l + off1,
            HDIM, 0, e,
            (bf16*)mh, (bf16*)ml, nullptr, nullptr);
        moe_gemm<<<dim3(NTOK / 128, HDIM / 128), 128, SMEM>>>(
            (const bf16*)mh, (const bf16*)ml,
            (const bf16*)w2h + off2, (const bf16*)w2l + off2,
            IDIM, 1, e,
            nullptr, nullptr, outp, (const float*)pp);
    }
}